// round 1
// baseline (speedup 1.0000x reference)
#include <cuda_runtime.h>
#include <cuda_fp16.h>
#include <math.h>

#define BB 2
#define SS 2048
#define HH 16
#define DD 128
#define BM 64
#define BN 64
#define NTHREADS 128
#define SPITCH (DD + 8)   // half elements per smem row; pad 8 halves -> conflict-free frag loads

// fp16 repacked tensors, [B, H, S, D] layout (head-major so K/V tiles are contiguous)
__device__ __half g_Q[(size_t)BB * HH * SS * DD];
__device__ __half g_K[(size_t)BB * HH * SS * DD];
__device__ __half g_V[(size_t)BB * HH * SS * DD];

// ---------------------------------------------------------------------------
// Repack: fp32 [B,S,H,D] -> fp16 [B,H,S,D]. One thread per 4 elements.
// Total elements per tensor = 2*2048*16*128 = 8388608 (exactly 8192*256*4).
// ---------------------------------------------------------------------------
__global__ void repack_kernel(const float* __restrict__ q,
                              const float* __restrict__ k,
                              const float* __restrict__ v) {
    size_t idx = (size_t)blockIdx.x * blockDim.x + threadIdx.x;
    size_t e = idx * 4;                 // linear index into [B,S,H,D]
    int d = (int)(e % DD);
    size_t t = e / DD;
    int h = (int)(t % HH); t /= HH;
    int s = (int)(t % SS);
    int b = (int)(t / SS);
    size_t o = (((size_t)b * HH + h) * SS + s) * DD + d;   // [B,H,S,D]

    float4 f;
    __half2 h0, h1;
    uint2 u;

    f = *(const float4*)(q + e);
    h0 = __floats2half2_rn(f.x, f.y);
    h1 = __floats2half2_rn(f.z, f.w);
    u.x = *reinterpret_cast<unsigned*>(&h0);
    u.y = *reinterpret_cast<unsigned*>(&h1);
    *(uint2*)(g_Q + o) = u;

    f = *(const float4*)(k + e);
    h0 = __floats2half2_rn(f.x, f.y);
    h1 = __floats2half2_rn(f.z, f.w);
    u.x = *reinterpret_cast<unsigned*>(&h0);
    u.y = *reinterpret_cast<unsigned*>(&h1);
    *(uint2*)(g_K + o) = u;

    f = *(const float4*)(v + e);
    h0 = __floats2half2_rn(f.x, f.y);
    h1 = __floats2half2_rn(f.z, f.w);
    u.x = *reinterpret_cast<unsigned*>(&h0);
    u.y = *reinterpret_cast<unsigned*>(&h1);
    *(uint2*)(g_V + o) = u;
}

// ---------------------------------------------------------------------------
// mma.sync m16n8k16 fp16 -> fp32 accumulate
// ---------------------------------------------------------------------------
__device__ __forceinline__ void mma16816(float* c, const unsigned* a,
                                         unsigned b0, unsigned b1) {
    asm volatile(
        "mma.sync.aligned.m16n8k16.row.col.f32.f16.f16.f32 "
        "{%0,%1,%2,%3}, {%4,%5,%6,%7}, {%8,%9}, {%0,%1,%2,%3};\n"
        : "+f"(c[0]), "+f"(c[1]), "+f"(c[2]), "+f"(c[3])
        : "r"(a[0]), "r"(a[1]), "r"(a[2]), "r"(a[3]), "r"(b0), "r"(b1));
}

__device__ __forceinline__ unsigned h2u(__half2 x) {
    return *reinterpret_cast<unsigned*>(&x);
}

// ---------------------------------------------------------------------------
// Flash attention (causal + ALiBi-sqrt bias), log2-domain online softmax.
// Grid: (S/BM, B*H). 4 warps; warp w owns rows [w*16, w*16+16) of the M-block.
// ---------------------------------------------------------------------------
__global__ void __launch_bounds__(NTHREADS)
fa_kernel(float* __restrict__ out) {
    __shared__ __half sK[BN * SPITCH];
    __shared__ __half sV[BN * SPITCH];

    const int mb = blockIdx.x;
    const int bh = blockIdx.y;
    const int b = bh / HH, h = bh % HH;
    const int tid = threadIdx.x;
    const int w = tid >> 5, lane = tid & 31;
    const int g = lane >> 2, tig = lane & 3;
    const int m0 = mb * BM;
    const int mrow = m0 + w * 16 + g;    // global row for the "g" half; +8 for other half

    // log2-domain constants: score2 = dot * QSCALE2 - slope2 * sqrt(i-j)
    const float L2E = 1.4426950408889634f;
    const float QSCALE2 = 0.08838834764831843f * L2E;        // (1/sqrt(128)) * log2(e)
    const float slope2 = exp2f(-0.5f * (float)(h + 1)) * L2E; // slope_h * log2(e)

    const __half* Qbase = g_Q + ((size_t)b * HH + h) * SS * DD;
    const __half* Kbase = g_K + ((size_t)b * HH + h) * SS * DD;
    const __half* Vbase = g_V + ((size_t)b * HH + h) * SS * DD;

    // --- Q fragments, register resident: 16 rows x 128 cols per warp ---
    unsigned qf[8][4];
    {
        const __half* q0 = Qbase + (size_t)mrow * DD;
        const __half* q1 = q0 + 8 * DD;
#pragma unroll
        for (int kt = 0; kt < 8; kt++) {
            qf[kt][0] = *(const unsigned*)(q0 + kt * 16 + 2 * tig);
            qf[kt][1] = *(const unsigned*)(q1 + kt * 16 + 2 * tig);
            qf[kt][2] = *(const unsigned*)(q0 + kt * 16 + 2 * tig + 8);
            qf[kt][3] = *(const unsigned*)(q1 + kt * 16 + 2 * tig + 8);
        }
    }

    float oacc[16][4];
#pragma unroll
    for (int i = 0; i < 16; i++)
#pragma unroll
        for (int j = 0; j < 4; j++) oacc[i][j] = 0.f;

    float mrun[2] = {-INFINITY, -INFINITY};
    float lrun[2] = {0.f, 0.f};

    const int ntiles = mb + 1;   // causal: only key blocks with n0 <= m0+BM-1
    for (int nt = 0; nt < ntiles; nt++) {
        const int n0 = nt * BN;

        __syncthreads();   // previous tile's consumers done before overwrite
        {
            const __half* kg = Kbase + (size_t)n0 * DD;
            const __half* vg = Vbase + (size_t)n0 * DD;
#pragma unroll
            for (int it = 0; it < 8; it++) {
                int e = it * NTHREADS + tid;   // 0..1023 -> 64 rows x 16 segs of 8 halves
                int r = e >> 4;
                int sg = e & 15;
                *(uint4*)&sK[r * SPITCH + sg * 8] = *(const uint4*)(kg + r * DD + sg * 8);
                *(uint4*)&sV[r * SPITCH + sg * 8] = *(const uint4*)(vg + r * DD + sg * 8);
            }
        }
        __syncthreads();

        // --- S = Q K^T : 16x64 per warp ---
        float sacc[8][4];
#pragma unroll
        for (int i = 0; i < 8; i++)
#pragma unroll
            for (int j = 0; j < 4; j++) sacc[i][j] = 0.f;

#pragma unroll
        for (int nf = 0; nf < 8; nf++) {
            const __half* kp = &sK[(nf * 8 + g) * SPITCH];
#pragma unroll
            for (int kt = 0; kt < 8; kt++) {
                unsigned b0 = *(const unsigned*)(kp + kt * 16 + 2 * tig);
                unsigned b1 = *(const unsigned*)(kp + kt * 16 + 2 * tig + 8);
                mma16816(sacc[nf], qf[kt], b0, b1);
            }
        }

        // --- bias + mask + online softmax (log2 domain) ---
#pragma unroll
        for (int hf = 0; hf < 2; hf++) {
            const int r = mrow + hf * 8;
            float tmax = -INFINITY;
#pragma unroll
            for (int nf = 0; nf < 8; nf++) {
#pragma unroll
                for (int j = 0; j < 2; j++) {
                    int c = n0 + nf * 8 + 2 * tig + j;
                    int dd2 = r - c;
                    float s2;
                    if (dd2 < 0) {
                        s2 = -INFINITY;
                    } else {
                        s2 = sacc[nf][hf * 2 + j] * QSCALE2
                           - slope2 * sqrtf((float)dd2);
                    }
                    sacc[nf][hf * 2 + j] = s2;
                    tmax = fmaxf(tmax, s2);
                }
            }
            tmax = fmaxf(tmax, __shfl_xor_sync(0xffffffffu, tmax, 1));
            tmax = fmaxf(tmax, __shfl_xor_sync(0xffffffffu, tmax, 2));

            float mnew = fmaxf(mrun[hf], tmax);
            float alpha = exp2f(mrun[hf] - mnew);
            mrun[hf] = mnew;

            float rsum = 0.f;
#pragma unroll
            for (int nf = 0; nf < 8; nf++) {
#pragma unroll
                for (int j = 0; j < 2; j++) {
                    float p = exp2f(sacc[nf][hf * 2 + j] - mnew);
                    sacc[nf][hf * 2 + j] = p;
                    rsum += p;
                }
            }
            rsum += __shfl_xor_sync(0xffffffffu, rsum, 1);
            rsum += __shfl_xor_sync(0xffffffffu, rsum, 2);
            lrun[hf] = lrun[hf] * alpha + rsum;

#pragma unroll
            for (int dt = 0; dt < 16; dt++) {
                oacc[dt][hf * 2 + 0] *= alpha;
                oacc[dt][hf * 2 + 1] *= alpha;
            }
        }

        // --- O += P V : reuse S accumulator layout as A fragments ---
#pragma unroll
        for (int kt = 0; kt < 4; kt++) {
            unsigned pa[4];
            pa[0] = h2u(__floats2half2_rn(sacc[2 * kt][0], sacc[2 * kt][1]));
            pa[1] = h2u(__floats2half2_rn(sacc[2 * kt][2], sacc[2 * kt][3]));
            pa[2] = h2u(__floats2half2_rn(sacc[2 * kt + 1][0], sacc[2 * kt + 1][1]));
            pa[3] = h2u(__floats2half2_rn(sacc[2 * kt + 1][2], sacc[2 * kt + 1][3]));
            const int r0 = kt * 16 + 2 * tig;
#pragma unroll
            for (int dt = 0; dt < 16; dt++) {
                int dc = dt * 8 + g;
                unsigned b0 = h2u(__halves2half2(sV[(r0    ) * SPITCH + dc],
                                                 sV[(r0 + 1) * SPITCH + dc]));
                unsigned b1 = h2u(__halves2half2(sV[(r0 + 8) * SPITCH + dc],
                                                 sV[(r0 + 9) * SPITCH + dc]));
                mma16816(oacc[dt], pa, b0, b1);
            }
        }
    }

    // --- epilogue: normalize + store to [B,S,H,D] fp32 ---
#pragma unroll
    for (int hf = 0; hf < 2; hf++) {
        float inv = 1.0f / lrun[hf];
        int r = mrow + hf * 8;
        float* op = out + (((size_t)b * SS + r) * HH + h) * DD;
#pragma unroll
        for (int dt = 0; dt < 16; dt++) {
            float2 v2 = make_float2(oacc[dt][hf * 2] * inv,
                                    oacc[dt][hf * 2 + 1] * inv);
            *(float2*)(op + dt * 8 + 2 * tig) = v2;
        }
    }
}

// ---------------------------------------------------------------------------
extern "C" void kernel_launch(void* const* d_in, const int* in_sizes, int n_in,
                              void* d_out, int out_size) {
    const float* q = (const float*)d_in[0];
    const float* k = (const float*)d_in[1];
    const float* v = (const float*)d_in[2];
    float* out = (float*)d_out;

    const size_t total4 = (size_t)BB * SS * HH * DD / 4;   // 2097152
    repack_kernel<<<(unsigned)(total4 / 256), 256>>>(q, k, v);

    dim3 grid(SS / BM, BB * HH);
    fa_kernel<<<grid, NTHREADS>>>(out);
}

// round 2
// speedup vs baseline: 2.0105x; 2.0105x over previous
#include <cuda_runtime.h>
#include <cuda_fp16.h>
#include <math.h>

#define BB 2
#define SS 2048
#define HH 16
#define DD 128
#define BM 64
#define BN 64
#define NTHREADS 128
#define SPITCH 136                 // halves per smem row (128 + 8 pad) -> conflict-free ldmatrix
#define STAGE (BN * SPITCH)        // halves per tensor per stage = 8704
#define SMEM_BYTES (4 * STAGE * 2 + SS * 4)   // 2-stage K + V (69632 B) + bias table (8192 B)

// fp16 repacked tensors, [B, H, S, D] layout (head-major so K/V tiles are contiguous)
__device__ __half g_Q[(size_t)BB * HH * SS * DD];
__device__ __half g_K[(size_t)BB * HH * SS * DD];
__device__ __half g_V[(size_t)BB * HH * SS * DD];

// ---------------------------------------------------------------------------
// Repack: fp32 [B,S,H,D] -> fp16 [B,H,S,D]. One thread per 4 elements.
// ---------------------------------------------------------------------------
__global__ void repack_kernel(const float* __restrict__ q,
                              const float* __restrict__ k,
                              const float* __restrict__ v) {
    size_t idx = (size_t)blockIdx.x * blockDim.x + threadIdx.x;
    size_t e = idx * 4;
    int d = (int)(e % DD);
    size_t t = e / DD;
    int h = (int)(t % HH); t /= HH;
    int s = (int)(t % SS);
    int b = (int)(t / SS);
    size_t o = (((size_t)b * HH + h) * SS + s) * DD + d;

    float4 f;
    __half2 h0, h1;
    uint2 u;

    f = *(const float4*)(q + e);
    h0 = __floats2half2_rn(f.x, f.y); h1 = __floats2half2_rn(f.z, f.w);
    u.x = *reinterpret_cast<unsigned*>(&h0); u.y = *reinterpret_cast<unsigned*>(&h1);
    *(uint2*)(g_Q + o) = u;

    f = *(const float4*)(k + e);
    h0 = __floats2half2_rn(f.x, f.y); h1 = __floats2half2_rn(f.z, f.w);
    u.x = *reinterpret_cast<unsigned*>(&h0); u.y = *reinterpret_cast<unsigned*>(&h1);
    *(uint2*)(g_K + o) = u;

    f = *(const float4*)(v + e);
    h0 = __floats2half2_rn(f.x, f.y); h1 = __floats2half2_rn(f.z, f.w);
    u.x = *reinterpret_cast<unsigned*>(&h0); u.y = *reinterpret_cast<unsigned*>(&h1);
    *(uint2*)(g_V + o) = u;
}

// ---------------------------------------------------------------------------
// PTX helpers
// ---------------------------------------------------------------------------
__device__ __forceinline__ void mma16816(float* c, const unsigned* a,
                                         unsigned b0, unsigned b1) {
    asm volatile(
        "mma.sync.aligned.m16n8k16.row.col.f32.f16.f16.f32 "
        "{%0,%1,%2,%3}, {%4,%5,%6,%7}, {%8,%9}, {%0,%1,%2,%3};\n"
        : "+f"(c[0]), "+f"(c[1]), "+f"(c[2]), "+f"(c[3])
        : "r"(a[0]), "r"(a[1]), "r"(a[2]), "r"(a[3]), "r"(b0), "r"(b1));
}

__device__ __forceinline__ void ldsm_x4(unsigned& r0, unsigned& r1,
                                        unsigned& r2, unsigned& r3, const void* p) {
    unsigned a = (unsigned)__cvta_generic_to_shared(p);
    asm volatile("ldmatrix.sync.aligned.m8n8.x4.shared.b16 {%0,%1,%2,%3}, [%4];\n"
                 : "=r"(r0), "=r"(r1), "=r"(r2), "=r"(r3) : "r"(a));
}

__device__ __forceinline__ void ldsm_x4_t(unsigned& r0, unsigned& r1,
                                          unsigned& r2, unsigned& r3, const void* p) {
    unsigned a = (unsigned)__cvta_generic_to_shared(p);
    asm volatile("ldmatrix.sync.aligned.m8n8.x4.trans.shared.b16 {%0,%1,%2,%3}, [%4];\n"
                 : "=r"(r0), "=r"(r1), "=r"(r2), "=r"(r3) : "r"(a));
}

__device__ __forceinline__ void cp16(void* s, const void* g) {
    unsigned a = (unsigned)__cvta_generic_to_shared(s);
    asm volatile("cp.async.cg.shared.global [%0], [%1], 16;\n" :: "r"(a), "l"(g));
}
__device__ __forceinline__ void cp_commit() { asm volatile("cp.async.commit_group;\n"); }
__device__ __forceinline__ void cp_wait1() { asm volatile("cp.async.wait_group 1;\n"); }
__device__ __forceinline__ void cp_wait0() { asm volatile("cp.async.wait_group 0;\n"); }

__device__ __forceinline__ unsigned h2ex2(unsigned x) {
    unsigned r; asm("ex2.approx.f16x2 %0, %1;" : "=r"(r) : "r"(x)); return r;
}
__device__ __forceinline__ float fex2(float x) {
    float r; asm("ex2.approx.f32 %0, %1;" : "=f"(r) : "f"(x)); return r;
}
__device__ __forceinline__ float fsqrt(float x) {
    float r; asm("sqrt.approx.f32 %0, %1;" : "=f"(r) : "f"(x)); return r;
}
__device__ __forceinline__ unsigned h2u(__half2 x) {
    return *reinterpret_cast<unsigned*>(&x);
}

// ---------------------------------------------------------------------------
// Flash attention (causal + ALiBi-sqrt), log2-domain online softmax.
// Grid (S/BM, B*H), 128 threads; warp w owns rows [w*16, w*16+16) of the M-block.
// 2-stage cp.async double buffer; ldmatrix for all smem fragments.
// ---------------------------------------------------------------------------
__global__ void __launch_bounds__(NTHREADS, 2)
fa_kernel(float* __restrict__ out) {
    extern __shared__ __half smem[];
    __half* sK = smem;                  // [2][STAGE]
    __half* sV = smem + 2 * STAGE;      // [2][STAGE]
    float* tab = (float*)(smem + 4 * STAGE);   // tab[d] = slope2 * sqrt(d), d in [0, SS)

    const int mb = gridDim.x - 1 - blockIdx.x;   // longest CTAs launch first
    const int bh = blockIdx.y;
    const int b = bh / HH, h = bh % HH;
    const int tid = threadIdx.x;
    const int w = tid >> 5, lane = tid & 31;
    const int g = lane >> 2, tig = lane & 3;
    const int m0 = mb * BM;
    const int mrow = m0 + w * 16 + g;

    const float L2E = 1.4426950408889634f;
    const float QSCALE2 = 0.08838834764831843f * L2E;          // (1/sqrt(128)) * log2(e)
    const float slope2 = exp2f(-0.5f * (float)(h + 1)) * L2E;  // slope_h * log2(e)
    const float NEGINF = __int_as_float(0xff800000);

    // bias table (per CTA): tab[d] = slope2 * sqrt(d)
    for (int i = tid; i < SS; i += NTHREADS) tab[i] = slope2 * fsqrt((float)i);

    const __half* Kbase = g_K + ((size_t)b * HH + h) * SS * DD;
    const __half* Vbase = g_V + ((size_t)b * HH + h) * SS * DD;

    // prefetch tile 0
    {
        const __half* kg = Kbase;
        const __half* vg = Vbase;
#pragma unroll
        for (int it = 0; it < 8; it++) {
            int e = it * NTHREADS + tid;
            int r = e >> 4, sg = e & 15;
            cp16(&sK[r * SPITCH + sg * 8], kg + r * DD + sg * 8);
            cp16(&sV[r * SPITCH + sg * 8], vg + r * DD + sg * 8);
        }
        cp_commit();
    }

    // Q fragments, register resident: 16 rows x 128 cols per warp
    unsigned qf[8][4];
    {
        const __half* q0 = g_Q + ((size_t)b * HH + h) * SS * DD + (size_t)mrow * DD;
        const __half* q1 = q0 + 8 * DD;
#pragma unroll
        for (int kt = 0; kt < 8; kt++) {
            qf[kt][0] = *(const unsigned*)(q0 + kt * 16 + 2 * tig);
            qf[kt][1] = *(const unsigned*)(q1 + kt * 16 + 2 * tig);
            qf[kt][2] = *(const unsigned*)(q0 + kt * 16 + 2 * tig + 8);
            qf[kt][3] = *(const unsigned*)(q1 + kt * 16 + 2 * tig + 8);
        }
    }

    float oacc[16][4];
#pragma unroll
    for (int i = 0; i < 16; i++)
#pragma unroll
        for (int j = 0; j < 4; j++) oacc[i][j] = 0.f;

    float mrun[2] = {NEGINF, NEGINF};
    float lrun[2] = {0.f, 0.f};

    const int ntiles = mb + 1;
    for (int nt = 0; nt < ntiles; nt++) {
        const int buf = nt & 1;

        // issue next tile's loads into the other buffer (safe: its previous
        // consumers finished before the end-of-iteration barrier)
        if (nt + 1 < ntiles) {
            const int n1 = (nt + 1) * BN;
            const int nb = (nt + 1) & 1;
            const __half* kg = Kbase + (size_t)n1 * DD;
            const __half* vg = Vbase + (size_t)n1 * DD;
#pragma unroll
            for (int it = 0; it < 8; it++) {
                int e = it * NTHREADS + tid;
                int r = e >> 4, sg = e & 15;
                cp16(&sK[nb * STAGE + r * SPITCH + sg * 8], kg + r * DD + sg * 8);
                cp16(&sV[nb * STAGE + r * SPITCH + sg * 8], vg + r * DD + sg * 8);
            }
            cp_commit();
            cp_wait1();
        } else {
            cp_wait0();
        }
        __syncthreads();   // tile nt visible to all warps (also covers tab on nt==0)

        const __half* Kb = sK + buf * STAGE;
        const __half* Vb = sV + buf * STAGE;
        const int n0 = nt * BN;

        // --- S = Q K^T : 16x64 per warp, B-frags via ldmatrix.x4 ---
        float sacc[8][4];
#pragma unroll
        for (int i = 0; i < 8; i++)
#pragma unroll
            for (int j = 0; j < 4; j++) sacc[i][j] = 0.f;

#pragma unroll
        for (int kt = 0; kt < 8; kt++) {
#pragma unroll
            for (int nf2 = 0; nf2 < 4; nf2++) {
                int row = nf2 * 16 + (lane & 7) + ((lane >> 4) << 3);
                int col = kt * 16 + ((lane >> 3) & 1) * 8;
                unsigned b0, b1, b2, b3;
                ldsm_x4(b0, b1, b2, b3, Kb + row * SPITCH + col);
                mma16816(sacc[2 * nf2], qf[kt], b0, b1);
                mma16816(sacc[2 * nf2 + 1], qf[kt], b2, b3);
            }
        }

        // --- bias + mask + online softmax (log2 domain, f16x2 exp) ---
        unsigned pfrag[4][4];   // A-fragments of P for the PV mma
#pragma unroll
        for (int hf = 0; hf < 2; hf++) {
            const int r = mrow + hf * 8;
            float tmax = NEGINF;
#pragma unroll
            for (int nf = 0; nf < 8; nf++) {
#pragma unroll
                for (int j = 0; j < 2; j++) {
                    int c = n0 + nf * 8 + 2 * tig + j;
                    int dd2 = r - c;
                    float bias = tab[dd2 < 0 ? 0 : dd2];
                    float s2 = (dd2 < 0) ? NEGINF
                                         : fmaf(sacc[nf][hf * 2 + j], QSCALE2, -bias);
                    sacc[nf][hf * 2 + j] = s2;
                    tmax = fmaxf(tmax, s2);
                }
            }
            tmax = fmaxf(tmax, __shfl_xor_sync(0xffffffffu, tmax, 1));
            tmax = fmaxf(tmax, __shfl_xor_sync(0xffffffffu, tmax, 2));

            float mnew = fmaxf(mrun[hf], tmax);
            float alpha = fex2(mrun[hf] - mnew);
            mrun[hf] = mnew;

            float rsum = 0.f;
#pragma unroll
            for (int nf = 0; nf < 8; nf++) {
                unsigned ph = h2ex2(h2u(__floats2half2_rn(
                    sacc[nf][hf * 2 + 0] - mnew, sacc[nf][hf * 2 + 1] - mnew)));
                pfrag[nf >> 1][((nf & 1) << 1) | hf] = ph;
                float2 pf = __half22float2(*reinterpret_cast<__half2*>(&ph));
                rsum += pf.x + pf.y;
            }
            rsum += __shfl_xor_sync(0xffffffffu, rsum, 1);
            rsum += __shfl_xor_sync(0xffffffffu, rsum, 2);
            lrun[hf] = lrun[hf] * alpha + rsum;

#pragma unroll
            for (int dt = 0; dt < 16; dt++) {
                oacc[dt][hf * 2 + 0] *= alpha;
                oacc[dt][hf * 2 + 1] *= alpha;
            }
        }

        // --- O += P V : B-frags via ldmatrix.x4.trans ---
#pragma unroll
        for (int kt = 0; kt < 4; kt++) {
#pragma unroll
            for (int dt2 = 0; dt2 < 8; dt2++) {
                int row = kt * 16 + (lane & 15);
                int col = dt2 * 16 + ((lane >> 4) << 3);
                unsigned v0, v1, v2, v3;
                ldsm_x4_t(v0, v1, v2, v3, Vb + row * SPITCH + col);
                mma16816(oacc[2 * dt2], pfrag[kt], v0, v1);
                mma16816(oacc[2 * dt2 + 1], pfrag[kt], v2, v3);
            }
        }

        __syncthreads();   // all warps done with buf before it is refilled
    }

    // --- epilogue: normalize + store to [B,S,H,D] fp32 ---
#pragma unroll
    for (int hf = 0; hf < 2; hf++) {
        float inv = 1.0f / lrun[hf];
        int r = mrow + hf * 8;
        float* op = out + (((size_t)b * SS + r) * HH + h) * DD;
#pragma unroll
        for (int dt = 0; dt < 16; dt++) {
            float2 v2 = make_float2(oacc[dt][hf * 2] * inv,
                                    oacc[dt][hf * 2 + 1] * inv);
            *(float2*)(op + dt * 8 + 2 * tig) = v2;
        }
    }
}

// ---------------------------------------------------------------------------
extern "C" void kernel_launch(void* const* d_in, const int* in_sizes, int n_in,
                              void* d_out, int out_size) {
    const float* q = (const float*)d_in[0];
    const float* k = (const float*)d_in[1];
    const float* v = (const float*)d_in[2];
    float* out = (float*)d_out;

    const size_t total4 = (size_t)BB * SS * HH * DD / 4;
    repack_kernel<<<(unsigned)(total4 / 256), 256>>>(q, k, v);

    cudaFuncSetAttribute(fa_kernel, cudaFuncAttributeMaxDynamicSharedMemorySize,
                         SMEM_BYTES);
    dim3 grid(SS / BM, BB * HH);
    fa_kernel<<<grid, NTHREADS, SMEM_BYTES>>>(out);
}